// round 2
// baseline (speedup 1.0000x reference)
#include <cuda_runtime.h>
#include <cstdint>

// Problem constants
#define BATCH 64
#define SEQ   512
#define EMB   256
#define DOUT  512
#define KBIG  (6 * EMB)   // 1536 = 6 combined taps * EMB

// Combined steady-state weights: Wbig[d][tt*EMB + e] = Weff[t=tt-2][d][e]
__device__ float g_Wbig[DOUT * KBIG];   // 3 MB scratch (static, no allocs)
__device__ float g_bias[DOUT];

// ---------------------------------------------------------------------------
// Fold the 4 conv branches + window sums into a single 6-tap conv weight.
// Steady-state (i in [2,255]) tap combinations:
//   t=-2: W4[0]
//   t=-1: W3[0] + W4[0]+W4[1]
//   t= 0: W1 + W2[0] + W3[0]+W3[1] + W4[0]+W4[1]+W4[2]
//   t=+1: W2[1] + W3[1]+W3[2] + W4[1]+W4[2]+W4[3]
//   t=+2: W3[2] + W4[2]+W4[3]
//   t=+3: W4[3]
// bias_s = b1 + b2 + 2*b3 + 3*b4
// ---------------------------------------------------------------------------
__global__ void combine_weights_kernel(
    const float* __restrict__ W1, const float* __restrict__ b1,
    const float* __restrict__ W2, const float* __restrict__ b2,
    const float* __restrict__ W3, const float* __restrict__ b3,
    const float* __restrict__ W4, const float* __restrict__ b4)
{
    int idx = blockIdx.x * blockDim.x + threadIdx.x;
    if (idx >= DOUT * EMB) return;
    int d = idx / EMB, e = idx % EMB;

    float w1  = W1[d * EMB + e];                       // (D,E,1)
    const float* w2 = W2 + (size_t)(d * EMB + e) * 2;  // (D,E,2)
    const float* w3 = W3 + (size_t)(d * EMB + e) * 3;  // (D,E,3)
    const float* w4 = W4 + (size_t)(d * EMB + e) * 4;  // (D,E,4)
    float w20 = w2[0], w21 = w2[1];
    float w30 = w3[0], w31 = w3[1], w32 = w3[2];
    float w40 = w4[0], w41 = w4[1], w42 = w4[2], w43 = w4[3];

    float* row = g_Wbig + (size_t)d * KBIG;
    row[0 * EMB + e] = w40;
    row[1 * EMB + e] = w30 + w40 + w41;
    row[2 * EMB + e] = w1 + w20 + w30 + w31 + w40 + w41 + w42;
    row[3 * EMB + e] = w21 + w31 + w32 + w41 + w42 + w43;
    row[4 * EMB + e] = w32 + w42 + w43;
    row[5 * EMB + e] = w43;

    if (e == 0) g_bias[d] = b1[d] + b2[d] + 2.0f * b3[d] + 3.0f * b4[d];
}

// ---------------------------------------------------------------------------
// Tiled fp32 GEMM: out[m][n] = sum_k A[m][k] * Bw[n][k] + bias[n]
// MODE 0: main region, i = m&255 in [0,256), K=1536, A row = x[b] + (i-2)*EMB
//         (front zero-padded via predicated loads), B = g_Wbig, bias = g_bias
// MODE 1: tail region, i = 256 + (m&255), K=256, B = W1, bias = b1
// 128x128 CTA tile, 16 k-slice, 8x8 per-thread, double-buffered smem.
// ---------------------------------------------------------------------------
template<int MODE>
__global__ void __launch_bounds__(256, 2) gemm_kernel(
    const float* __restrict__ X,
    const float* __restrict__ Bw_param,
    const float* __restrict__ bias_param,
    float* __restrict__ out)
{
    constexpr int KT = (MODE == 0) ? KBIG : EMB;
    constexpr int NK = KT / 16;

    const float* Bw   = (MODE == 0) ? g_Wbig : Bw_param;
    const float* bias = (MODE == 0) ? g_bias : bias_param;

    __shared__ float As[2][16][128];
    __shared__ float Bs[2][16][128];

    int tid = threadIdx.x;
    int tx = tid & 15, ty = tid >> 4;
    int m0 = blockIdx.x * 128;
    int n0 = blockIdx.y * 128;

    // Loader mapping: thread handles rows (ra, ra+64), 4-float chunk ca
    int ra = tid >> 2;          // 0..63
    int ca = (tid & 3) * 4;     // 0,4,8,12

    const float* aptr[2];
    int minK[2];
    const float* bptr[2];
#pragma unroll
    for (int h = 0; h < 2; h++) {
        int m = m0 + ra + h * 64;
        int b = m >> 8;
        int i = (m & 255) + (MODE == 1 ? 256 : 0);
        if (MODE == 0) {
            aptr[h] = X + (size_t)b * (SEQ * EMB) + (i - 2) * EMB;
            minK[h] = (i >= 2) ? 0 : (2 - i) * EMB;
        } else {
            aptr[h] = X + (size_t)b * (SEQ * EMB) + i * EMB;
            minK[h] = 0;
        }
        int n = n0 + ra + h * 64;
        bptr[h] = Bw + (size_t)n * KT;
    }

    float acc[8][8];
#pragma unroll
    for (int mm = 0; mm < 8; mm++)
#pragma unroll
        for (int nn = 0; nn < 8; nn++) acc[mm][nn] = 0.0f;

    float4 av[2], bv[2];

    // Prologue: load tile 0
#pragma unroll
    for (int h = 0; h < 2; h++) {
        int kg = 0 + ca;
        if (MODE == 0 && kg < minK[h]) {
            av[h] = make_float4(0.f, 0.f, 0.f, 0.f);
        } else {
            av[h] = *reinterpret_cast<const float4*>(aptr[h] + kg);
        }
        bv[h] = *reinterpret_cast<const float4*>(bptr[h] + kg);
    }
#pragma unroll
    for (int h = 0; h < 2; h++) {
        int r = ra + h * 64;
        As[0][ca + 0][r] = av[h].x; As[0][ca + 1][r] = av[h].y;
        As[0][ca + 2][r] = av[h].z; As[0][ca + 3][r] = av[h].w;
        Bs[0][ca + 0][r] = bv[h].x; Bs[0][ca + 1][r] = bv[h].y;
        Bs[0][ca + 2][r] = bv[h].z; Bs[0][ca + 3][r] = bv[h].w;
    }
    __syncthreads();

    for (int kt = 0; kt < NK; ++kt) {
        int cur = kt & 1, nxt = cur ^ 1;

        // Prefetch next tile into registers (overlapped with compute below)
        if (kt + 1 < NK) {
            int kg = (kt + 1) * 16 + ca;
#pragma unroll
            for (int h = 0; h < 2; h++) {
                if (MODE == 0 && kg < minK[h]) {
                    av[h] = make_float4(0.f, 0.f, 0.f, 0.f);
                } else {
                    av[h] = *reinterpret_cast<const float4*>(aptr[h] + kg);
                }
                bv[h] = *reinterpret_cast<const float4*>(bptr[h] + kg);
            }
        }

        // Compute on current buffer
#pragma unroll
        for (int k = 0; k < 16; ++k) {
            float af[8], bf[8];
            *reinterpret_cast<float4*>(&af[0]) =
                *reinterpret_cast<const float4*>(&As[cur][k][ty * 8]);
            *reinterpret_cast<float4*>(&af[4]) =
                *reinterpret_cast<const float4*>(&As[cur][k][ty * 8 + 4]);
            *reinterpret_cast<float4*>(&bf[0]) =
                *reinterpret_cast<const float4*>(&Bs[cur][k][tx * 8]);
            *reinterpret_cast<float4*>(&bf[4]) =
                *reinterpret_cast<const float4*>(&Bs[cur][k][tx * 8 + 4]);
#pragma unroll
            for (int mm = 0; mm < 8; mm++)
#pragma unroll
                for (int nn = 0; nn < 8; nn++)
                    acc[mm][nn] = fmaf(af[mm], bf[nn], acc[mm][nn]);
        }

        // Store prefetched tile into next buffer
        if (kt + 1 < NK) {
#pragma unroll
            for (int h = 0; h < 2; h++) {
                int r = ra + h * 64;
                As[nxt][ca + 0][r] = av[h].x; As[nxt][ca + 1][r] = av[h].y;
                As[nxt][ca + 2][r] = av[h].z; As[nxt][ca + 3][r] = av[h].w;
                Bs[nxt][ca + 0][r] = bv[h].x; Bs[nxt][ca + 1][r] = bv[h].y;
                Bs[nxt][ca + 2][r] = bv[h].z; Bs[nxt][ca + 3][r] = bv[h].w;
            }
        }
        __syncthreads();
    }

    // Epilogue: add bias, write out[b][i][n]
    float bvec[8];
#pragma unroll
    for (int nn = 0; nn < 8; nn++) bvec[nn] = bias[n0 + tx * 8 + nn];

#pragma unroll
    for (int mm = 0; mm < 8; mm++) {
        int m = m0 + ty * 8 + mm;
        int b = m >> 8;
        int i = (m & 255) + (MODE == 1 ? 256 : 0);
        float* orow = out + ((size_t)b * SEQ + i) * DOUT + n0 + tx * 8;
        float4 o0, o1;
        o0.x = acc[mm][0] + bvec[0]; o0.y = acc[mm][1] + bvec[1];
        o0.z = acc[mm][2] + bvec[2]; o0.w = acc[mm][3] + bvec[3];
        o1.x = acc[mm][4] + bvec[4]; o1.y = acc[mm][5] + bvec[5];
        o1.z = acc[mm][6] + bvec[6]; o1.w = acc[mm][7] + bvec[7];
        *reinterpret_cast<float4*>(orow)     = o0;
        *reinterpret_cast<float4*>(orow + 4) = o1;
    }
}

// ---------------------------------------------------------------------------
// Edge fix: the steady-state GEMM applied at i=0,1 with zero-padded x
// overcounts the zero-padded conv terms (and their biases). Subtract:
//   i=0: conv3_pad[-1] + conv4_pad[-1] + conv4_pad[-2]
//      = x0*(W3[1]+W4[1]+W4[2]) + x1*(W3[2]+W4[2]+W4[3]) + x2*W4[3] + b3 + 2*b4
//   i=1: conv4_pad[-1] = x0*W4[1] + x1*W4[2] + x2*W4[3] + b4
// ---------------------------------------------------------------------------
__global__ void edge_fix_kernel(
    const float* __restrict__ X,
    const float* __restrict__ W3, const float* __restrict__ b3,
    const float* __restrict__ W4, const float* __restrict__ b4,
    float* __restrict__ out)
{
    __shared__ float sx[3][EMB];
    int b = blockIdx.x;
    int d = threadIdx.x;   // 512 threads = DOUT

    for (int idx = d; idx < 3 * EMB; idx += blockDim.x)
        sx[idx / EMB][idx % EMB] = X[(size_t)b * SEQ * EMB + idx];
    __syncthreads();

    float acc0 = b3[d] + 2.0f * b4[d];
    float acc1 = b4[d];
    const float* w3 = W3 + (size_t)d * EMB * 3;
    const float* w4 = W4 + (size_t)d * EMB * 4;
#pragma unroll 4
    for (int e = 0; e < EMB; e++) {
        float x0 = sx[0][e], x1 = sx[1][e], x2 = sx[2][e];
        float w31 = w3[e * 3 + 1], w32 = w3[e * 3 + 2];
        float w41 = w4[e * 4 + 1], w42 = w4[e * 4 + 2], w43 = w4[e * 4 + 3];
        acc0 = fmaf(x0, w31 + w41 + w42, acc0);
        acc0 = fmaf(x1, w32 + w42 + w43, acc0);
        acc0 = fmaf(x2, w43, acc0);
        acc1 = fmaf(x0, w41, acc1);
        acc1 = fmaf(x1, w42, acc1);
        acc1 = fmaf(x2, w43, acc1);
    }
    out[((size_t)b * SEQ + 0) * DOUT + d] -= acc0;
    out[((size_t)b * SEQ + 1) * DOUT + d] -= acc1;
}

// ---------------------------------------------------------------------------
extern "C" void kernel_launch(void* const* d_in, const int* in_sizes, int n_in,
                              void* d_out, int out_size)
{
    const float* X  = (const float*)d_in[0];
    const float* W1 = (const float*)d_in[1];
    const float* b1 = (const float*)d_in[2];
    const float* W2 = (const float*)d_in[3];
    const float* b2 = (const float*)d_in[4];
    const float* W3 = (const float*)d_in[5];
    const float* b3 = (const float*)d_in[6];
    const float* W4 = (const float*)d_in[7];
    const float* b4 = (const float*)d_in[8];
    float* out = (float*)d_out;

    // 1. Fold all branches + window sums into 6-tap combined weights
    combine_weights_kernel<<<(DOUT * EMB + 255) / 256, 256>>>(
        W1, b1, W2, b2, W3, b3, W4, b4);

    // 2. Main region i in [0,256): M=16384, N=512, K=1536
    dim3 grid(128, 4);
    gemm_kernel<0><<<grid, 256>>>(X, nullptr, nullptr, out);

    // 3. Tail region i in [256,512): unigram only, K=256
    gemm_kernel<1><<<grid, 256>>>(X, W1, b1, out);

    // 4. Subtract zero-padding overcount at i=0,1
    edge_fix_kernel<<<BATCH, DOUT>>>(X, W3, b3, W4, b4, out);
}

// round 7
// speedup vs baseline: 1.4695x; 1.4695x over previous
#include <cuda_runtime.h>
#include <cstdint>

// Problem constants
#define BATCH 64
#define SEQ   512
#define EMB   256
#define DOUT  512
#define KBIG  (6 * EMB)   // 1536 = 6 combined taps * EMB
#define KFIX  (3 * EMB)   // 768 = 3 taps of x used by edge corrections

// Combined steady-state weights: Wbig[d][tt*EMB + e] = Weff[t=tt-2][d][e]
__device__ float g_Wbig[DOUT * KBIG];    // 3 MB scratch (static, no allocs)
__device__ float g_bias[DOUT];
// Edge-correction combined weights (coalesced layout [d][t*EMB+e])
__device__ float g_Wfix0[DOUT * KFIX];   // i=0 correction coefficients
__device__ float g_Wfix1[DOUT * KFIX];   // i=1 correction coefficients
__device__ float g_bfix0[DOUT];
__device__ float g_bfix1[DOUT];

// ---------------------------------------------------------------------------
// Fold the 4 conv branches + window sums into a single 6-tap conv weight,
// and build the edge-correction weight rows.
// Steady-state (i in [2,255]) tap combinations:
//   t=-2: W4[0]
//   t=-1: W3[0] + W4[0]+W4[1]
//   t= 0: W1 + W2[0] + W3[0]+W3[1] + W4[0]+W4[1]+W4[2]
//   t=+1: W2[1] + W3[1]+W3[2] + W4[1]+W4[2]+W4[3]
//   t=+2: W3[2] + W4[2]+W4[3]
//   t=+3: W4[3]
// bias_s = b1 + b2 + 2*b3 + 3*b4
// Edge overcount (subtract after zero-padded steady GEMM):
//   i=0: x0*(W3[1]+W4[1]+W4[2]) + x1*(W3[2]+W4[2]+W4[3]) + x2*W4[3] + b3+2*b4
//   i=1: x0*W4[1] + x1*W4[2] + x2*W4[3] + b4
// ---------------------------------------------------------------------------
__global__ void combine_weights_kernel(
    const float* __restrict__ W1, const float* __restrict__ b1,
    const float* __restrict__ W2, const float* __restrict__ b2,
    const float* __restrict__ W3, const float* __restrict__ b3,
    const float* __restrict__ W4, const float* __restrict__ b4)
{
    int idx = blockIdx.x * blockDim.x + threadIdx.x;
    if (idx >= DOUT * EMB) return;
    int d = idx / EMB, e = idx % EMB;

    float w1  = W1[d * EMB + e];                       // (D,E,1)
    const float* w2 = W2 + (size_t)(d * EMB + e) * 2;  // (D,E,2)
    const float* w3 = W3 + (size_t)(d * EMB + e) * 3;  // (D,E,3)
    const float* w4 = W4 + (size_t)(d * EMB + e) * 4;  // (D,E,4)
    float w20 = w2[0], w21 = w2[1];
    float w30 = w3[0], w31 = w3[1], w32 = w3[2];
    float w40 = w4[0], w41 = w4[1], w42 = w4[2], w43 = w4[3];

    float* row = g_Wbig + (size_t)d * KBIG;
    row[0 * EMB + e] = w40;
    row[1 * EMB + e] = w30 + w40 + w41;
    row[2 * EMB + e] = w1 + w20 + w30 + w31 + w40 + w41 + w42;
    row[3 * EMB + e] = w21 + w31 + w32 + w41 + w42 + w43;
    row[4 * EMB + e] = w32 + w42 + w43;
    row[5 * EMB + e] = w43;

    float* f0 = g_Wfix0 + (size_t)d * KFIX;
    float* f1 = g_Wfix1 + (size_t)d * KFIX;
    f0[0 * EMB + e] = w31 + w41 + w42;
    f0[1 * EMB + e] = w32 + w42 + w43;
    f0[2 * EMB + e] = w43;
    f1[0 * EMB + e] = w41;
    f1[1 * EMB + e] = w42;
    f1[2 * EMB + e] = w43;

    if (e == 0) {
        g_bias[d]  = b1[d] + b2[d] + 2.0f * b3[d] + 3.0f * b4[d];
        g_bfix0[d] = b3[d] + 2.0f * b4[d];
        g_bfix1[d] = b4[d];
    }
}

// ---------------------------------------------------------------------------
// Unified tiled fp32 GEMM: out[m][n] = sum_k A[m][k] * Bw[n][k] + bias[n]
// blockIdx.z == 0: main region, i = m&255 in [0,256), K=1536,
//   A row = x[b] + (i-2)*EMB (front zero-padded via predicated loads),
//   B = g_Wbig, bias = g_bias
// blockIdx.z == 1: tail region, i = 256 + (m&255), K=256, B = W1, bias = b1
// 128x128 CTA tile, 16 k-slice, 8x8 per-thread, double-buffered smem.
// Single launch (1024 CTAs) reduces wave-quantization bubbles vs 2 launches.
// ---------------------------------------------------------------------------
__global__ void __launch_bounds__(256, 2) gemm_kernel(
    const float* __restrict__ X,
    const float* __restrict__ W1,
    const float* __restrict__ b1,
    float* __restrict__ out)
{
    const int mode = blockIdx.z;                 // 0 = main, 1 = tail
    const float* Bw   = (mode == 0) ? g_Wbig : W1;
    const float* bias = (mode == 0) ? g_bias : b1;
    const int KT = (mode == 0) ? KBIG : EMB;
    const int NK = KT >> 4;

    __shared__ float As[2][16][128];
    __shared__ float Bs[2][16][128];

    int tid = threadIdx.x;
    int tx = tid & 15, ty = tid >> 4;
    int m0 = blockIdx.x * 128;
    int n0 = blockIdx.y * 128;

    // Loader mapping: thread handles rows (ra, ra+64), 4-float chunk ca
    int ra = tid >> 2;          // 0..63
    int ca = (tid & 3) * 4;     // 0,4,8,12

    const float* aptr[2];
    int minK[2];
    const float* bptr[2];
#pragma unroll
    for (int h = 0; h < 2; h++) {
        int m = m0 + ra + h * 64;
        int b = m >> 8;
        int i = (m & 255) + (mode ? 256 : 0);
        if (mode == 0) {
            aptr[h] = X + (size_t)b * (SEQ * EMB) + (i - 2) * EMB;
            minK[h] = (i >= 2) ? 0 : (2 - i) * EMB;
        } else {
            aptr[h] = X + (size_t)b * (SEQ * EMB) + i * EMB;
            minK[h] = 0;
        }
        int n = n0 + ra + h * 64;
        bptr[h] = Bw + (size_t)n * KT;
    }

    float acc[8][8];
#pragma unroll
    for (int mm = 0; mm < 8; mm++)
#pragma unroll
        for (int nn = 0; nn < 8; nn++) acc[mm][nn] = 0.0f;

    float4 av[2], bv[2];

    // Prologue: load tile 0
#pragma unroll
    for (int h = 0; h < 2; h++) {
        int kg = ca;
        if (kg < minK[h]) {
            av[h] = make_float4(0.f, 0.f, 0.f, 0.f);
        } else {
            av[h] = *reinterpret_cast<const float4*>(aptr[h] + kg);
        }
        bv[h] = *reinterpret_cast<const float4*>(bptr[h] + kg);
    }
#pragma unroll
    for (int h = 0; h < 2; h++) {
        int r = ra + h * 64;
        As[0][ca + 0][r] = av[h].x; As[0][ca + 1][r] = av[h].y;
        As[0][ca + 2][r] = av[h].z; As[0][ca + 3][r] = av[h].w;
        Bs[0][ca + 0][r] = bv[h].x; Bs[0][ca + 1][r] = bv[h].y;
        Bs[0][ca + 2][r] = bv[h].z; Bs[0][ca + 3][r] = bv[h].w;
    }
    __syncthreads();

    for (int kt = 0; kt < NK; ++kt) {
        int cur = kt & 1, nxt = cur ^ 1;

        // Prefetch next tile into registers (overlapped with compute below)
        if (kt + 1 < NK) {
            int kg = (kt + 1) * 16 + ca;
#pragma unroll
            for (int h = 0; h < 2; h++) {
                if (kg < minK[h]) {
                    av[h] = make_float4(0.f, 0.f, 0.f, 0.f);
                } else {
                    av[h] = *reinterpret_cast<const float4*>(aptr[h] + kg);
                }
                bv[h] = *reinterpret_cast<const float4*>(bptr[h] + kg);
            }
        }

        // Compute on current buffer
#pragma unroll
        for (int k = 0; k < 16; ++k) {
            float af[8], bf[8];
            *reinterpret_cast<float4*>(&af[0]) =
                *reinterpret_cast<const float4*>(&As[cur][k][ty * 8]);
            *reinterpret_cast<float4*>(&af[4]) =
                *reinterpret_cast<const float4*>(&As[cur][k][ty * 8 + 4]);
            *reinterpret_cast<float4*>(&bf[0]) =
                *reinterpret_cast<const float4*>(&Bs[cur][k][tx * 8]);
            *reinterpret_cast<float4*>(&bf[4]) =
                *reinterpret_cast<const float4*>(&Bs[cur][k][tx * 8 + 4]);
#pragma unroll
            for (int mm = 0; mm < 8; mm++)
#pragma unroll
                for (int nn = 0; nn < 8; nn++)
                    acc[mm][nn] = fmaf(af[mm], bf[nn], acc[mm][nn]);
        }

        // Store prefetched tile into next buffer
        if (kt + 1 < NK) {
#pragma unroll
            for (int h = 0; h < 2; h++) {
                int r = ra + h * 64;
                As[nxt][ca + 0][r] = av[h].x; As[nxt][ca + 1][r] = av[h].y;
                As[nxt][ca + 2][r] = av[h].z; As[nxt][ca + 3][r] = av[h].w;
                Bs[nxt][ca + 0][r] = bv[h].x; Bs[nxt][ca + 1][r] = bv[h].y;
                Bs[nxt][ca + 2][r] = bv[h].z; Bs[nxt][ca + 3][r] = bv[h].w;
            }
        }
        __syncthreads();
    }

    // Epilogue: add bias, write out[b][i][n]
    float bvec[8];
#pragma unroll
    for (int nn = 0; nn < 8; nn++) bvec[nn] = bias[n0 + tx * 8 + nn];

#pragma unroll
    for (int mm = 0; mm < 8; mm++) {
        int m = m0 + ty * 8 + mm;
        int b = m >> 8;
        int i = (m & 255) + (mode ? 256 : 0);
        float* orow = out + ((size_t)b * SEQ + i) * DOUT + n0 + tx * 8;
        float4 o0, o1;
        o0.x = acc[mm][0] + bvec[0]; o0.y = acc[mm][1] + bvec[1];
        o0.z = acc[mm][2] + bvec[2]; o0.w = acc[mm][3] + bvec[3];
        o1.x = acc[mm][4] + bvec[4]; o1.y = acc[mm][5] + bvec[5];
        o1.z = acc[mm][6] + bvec[6]; o1.w = acc[mm][7] + bvec[7];
        *reinterpret_cast<float4*>(orow)     = o0;
        *reinterpret_cast<float4*>(orow + 4) = o1;
    }
}

// ---------------------------------------------------------------------------
// Edge fix, warp-per-output: subtract the zero-padding overcount at i=0,1.
// grid = (BATCH, DOUT/8), block = 256 (8 warps). Each warp handles one d:
// fully coalesced lane-strided reads of the precomputed fix-weight rows,
// x[b][0..2][:] staged in smem, butterfly shfl reduction.
// ---------------------------------------------------------------------------
__global__ void __launch_bounds__(256) edge_fix_kernel(
    const float* __restrict__ X,
    float* __restrict__ out)
{
    __shared__ float sx[KFIX];
    int b = blockIdx.x;
    int tid = threadIdx.x;
    int warp = tid >> 5, lane = tid & 31;
    int d = blockIdx.y * 8 + warp;

    for (int idx = tid; idx < KFIX; idx += blockDim.x)
        sx[idx] = X[(size_t)b * SEQ * EMB + idx];
    __syncthreads();

    const float* w0 = g_Wfix0 + (size_t)d * KFIX;
    const float* w1 = g_Wfix1 + (size_t)d * KFIX;
    float a0 = 0.0f, a1 = 0.0f;
#pragma unroll
    for (int t = 0; t < KFIX / 32; t++) {
        int k = lane + 32 * t;
        float xv = sx[k];
        a0 = fmaf(xv, w0[k], a0);
        a1 = fmaf(xv, w1[k], a1);
    }
#pragma unroll
    for (int off = 16; off; off >>= 1) {
        a0 += __shfl_xor_sync(0xFFFFFFFFu, a0, off);
        a1 += __shfl_xor_sync(0xFFFFFFFFu, a1, off);
    }
    if (lane == 0) {
        out[((size_t)b * SEQ + 0) * DOUT + d] -= a0 + g_bfix0[d];
        out[((size_t)b * SEQ + 1) * DOUT + d] -= a1 + g_bfix1[d];
    }
}

// ---------------------------------------------------------------------------
extern "C" void kernel_launch(void* const* d_in, const int* in_sizes, int n_in,
                              void* d_out, int out_size)
{
    const float* X  = (const float*)d_in[0];
    const float* W1 = (const float*)d_in[1];
    const float* b1 = (const float*)d_in[2];
    const float* W2 = (const float*)d_in[3];
    const float* b2 = (const float*)d_in[4];
    const float* W3 = (const float*)d_in[5];
    const float* b3 = (const float*)d_in[6];
    const float* W4 = (const float*)d_in[7];
    const float* b4 = (const float*)d_in[8];
    float* out = (float*)d_out;

    // 1. Fold all branches + window sums into combined weights (+ fix rows)
    combine_weights_kernel<<<(DOUT * EMB + 255) / 256, 256>>>(
        W1, b1, W2, b2, W3, b3, W4, b4);

    // 2. Both GEMM regions in ONE launch (z=0: main K=1536, z=1: tail K=256)
    dim3 grid(128, 4, 2);
    gemm_kernel<<<grid, 256>>>(X, W1, b1, out);

    // 3. Subtract zero-padding overcount at i=0,1 (warp-per-output dots)
    edge_fix_kernel<<<dim3(BATCH, DOUT / 8), 256>>>(X, out);
}

// round 10
// speedup vs baseline: 3.5428x; 2.4108x over previous
#include <cuda_runtime.h>
#include <cuda_bf16.h>
#include <cstdint>

// Problem constants
#define BATCH 64
#define SEQ   512
#define EMB   256
#define DOUT  512
#define KBIG  1536          // 6 combined taps * EMB
#define KFIX  768           // 3 taps of x used by edge corrections
#define SEQP  (SEQ + 2)     // X padded with 2 zero rows at front (per batch)

// ---------------- device scratch (static globals: allowed) ----------------
__device__ __nv_bfloat16 g_Xh[BATCH * SEQP * EMB];   // bf16 hi of padded X
__device__ __nv_bfloat16 g_Xl[BATCH * SEQP * EMB];   // bf16 lo of padded X
__device__ __nv_bfloat16 g_Wbh[DOUT * KBIG];         // combined weights hi
__device__ __nv_bfloat16 g_Wbl[DOUT * KBIG];         // combined weights lo
__device__ __nv_bfloat16 g_W1h[DOUT * EMB];          // unigram weights hi
__device__ __nv_bfloat16 g_W1l[DOUT * EMB];          // unigram weights lo
__device__ float g_bias[DOUT];
__device__ float g_Wfix0[DOUT * KFIX];
__device__ float g_Wfix1[DOUT * KFIX];
__device__ float g_bfix0[DOUT];
__device__ float g_bfix1[DOUT];

// ---------------- baseline-PTX helpers (no sm_103a-only features) ---------
__device__ __forceinline__ uint32_t smem_u32(const void* p) {
    uint32_t a;
    asm("{ .reg .u64 t; cvta.to.shared.u64 t, %1; cvt.u32.u64 %0, t; }"
        : "=r"(a) : "l"(p));
    return a;
}

#define CPASYNC16(dst, src) \
    asm volatile("cp.async.cg.shared.global [%0], [%1], 16;" \
                 :: "r"((uint32_t)(dst)), "l"(src) : "memory")
#define CP_COMMIT()  asm volatile("cp.async.commit_group;" ::: "memory")
#define CP_WAIT(n)   asm volatile("cp.async.wait_group %0;" :: "n"(n) : "memory")

#define LDSM4(r, addr) \
    asm volatile("ldmatrix.sync.aligned.m8n8.x4.shared.b16 {%0,%1,%2,%3}, [%4];" \
        : "=r"((r)[0]), "=r"((r)[1]), "=r"((r)[2]), "=r"((r)[3]) \
        : "r"((uint32_t)(addr)))

#define MMA_BF16(c, a, b0, b1) \
    asm volatile("mma.sync.aligned.m16n8k16.row.col.f32.bf16.bf16.f32 " \
        "{%0,%1,%2,%3}, {%4,%5,%6,%7}, {%8,%9}, {%0,%1,%2,%3};" \
        : "+f"((c)[0]), "+f"((c)[1]), "+f"((c)[2]), "+f"((c)[3]) \
        : "r"((a)[0]), "r"((a)[1]), "r"((a)[2]), "r"((a)[3]), \
          "r"(b0), "r"(b1))

__device__ __forceinline__ void bsplit(float v, __nv_bfloat16& h, __nv_bfloat16& l) {
    h = __float2bfloat16(v);
    l = __float2bfloat16(v - __bfloat162float(h));
}

// ---------------------------------------------------------------------------
// Fold the 4 conv branches + window sums into a 6-tap combined conv weight
// (bf16 hi/lo split), plus edge-correction rows (fp32).
// Steady-state (i in [2,255]) tap combinations:
//   t=-2: W4[0]
//   t=-1: W3[0] + W4[0]+W4[1]
//   t= 0: W1 + W2[0] + W3[0]+W3[1] + W4[0]+W4[1]+W4[2]
//   t=+1: W2[1] + W3[1]+W3[2] + W4[1]+W4[2]+W4[3]
//   t=+2: W3[2] + W4[2]+W4[3]
//   t=+3: W4[3]
// bias_s = b1 + b2 + 2*b3 + 3*b4
// ---------------------------------------------------------------------------
__global__ void combine_weights_kernel(
    const float* __restrict__ W1, const float* __restrict__ b1,
    const float* __restrict__ W2, const float* __restrict__ b2,
    const float* __restrict__ W3, const float* __restrict__ b3,
    const float* __restrict__ W4, const float* __restrict__ b4)
{
    int idx = blockIdx.x * blockDim.x + threadIdx.x;
    if (idx >= DOUT * EMB) return;
    int d = idx / EMB, e = idx % EMB;

    float w1  = W1[d * EMB + e];
    const float* w2 = W2 + (size_t)(d * EMB + e) * 2;
    const float* w3 = W3 + (size_t)(d * EMB + e) * 3;
    const float* w4 = W4 + (size_t)(d * EMB + e) * 4;
    float w20 = w2[0], w21 = w2[1];
    float w30 = w3[0], w31 = w3[1], w32 = w3[2];
    float w40 = w4[0], w41 = w4[1], w42 = w4[2], w43 = w4[3];

    float taps[6];
    taps[0] = w40;
    taps[1] = w30 + w40 + w41;
    taps[2] = w1 + w20 + w30 + w31 + w40 + w41 + w42;
    taps[3] = w21 + w31 + w32 + w41 + w42 + w43;
    taps[4] = w32 + w42 + w43;
    taps[5] = w43;
#pragma unroll
    for (int t = 0; t < 6; t++) {
        size_t o = (size_t)d * KBIG + t * EMB + e;
        bsplit(taps[t], g_Wbh[o], g_Wbl[o]);
    }
    bsplit(w1, g_W1h[d * EMB + e], g_W1l[d * EMB + e]);

    float* f0 = g_Wfix0 + (size_t)d * KFIX;
    float* f1 = g_Wfix1 + (size_t)d * KFIX;
    f0[0 * EMB + e] = w31 + w41 + w42;
    f0[1 * EMB + e] = w32 + w42 + w43;
    f0[2 * EMB + e] = w43;
    f1[0 * EMB + e] = w41;
    f1[1 * EMB + e] = w42;
    f1[2 * EMB + e] = w43;

    if (e == 0) {
        g_bias[d]  = b1[d] + b2[d] + 2.0f * b3[d] + 3.0f * b4[d];
        g_bfix0[d] = b3[d] + 2.0f * b4[d];
        g_bfix1[d] = b4[d];
    }
}

// ---------------------------------------------------------------------------
// Convert X (fp32) into padded bf16 hi/lo arrays: rows 0,1 zero, r>=2 = X[r-2].
// ---------------------------------------------------------------------------
__global__ void convert_x_kernel(const float* __restrict__ X)
{
    int u = blockIdx.x * blockDim.x + threadIdx.x;          // one float4 unit
    if (u >= BATCH * SEQP * EMB / 4) return;
    int e4  = u & 63;
    int row = u >> 6;            // b*SEQP + r
    int r   = row % SEQP;
    __nv_bfloat16 h[4], l[4];
    if (r < 2) {
#pragma unroll
        for (int j = 0; j < 4; j++) { h[j] = __float2bfloat16(0.f); l[j] = h[j]; }
    } else {
        int b = row / SEQP;
        float4 v = *reinterpret_cast<const float4*>(
            X + ((size_t)(b * SEQ + (r - 2))) * EMB + e4 * 4);
        float a[4] = {v.x, v.y, v.z, v.w};
#pragma unroll
        for (int j = 0; j < 4; j++) bsplit(a[j], h[j], l[j]);
    }
    size_t o = (size_t)row * EMB + e4 * 4;
    *reinterpret_cast<__nv_bfloat162*>(g_Xh + o)     = __halves2bfloat162(h[0], h[1]);
    *reinterpret_cast<__nv_bfloat162*>(g_Xh + o + 2) = __halves2bfloat162(h[2], h[3]);
    *reinterpret_cast<__nv_bfloat162*>(g_Xl + o)     = __halves2bfloat162(l[0], l[1]);
    *reinterpret_cast<__nv_bfloat162*>(g_Xl + o + 2) = __halves2bfloat162(l[2], l[3]);
}

// ---------------------------------------------------------------------------
// Warp-level HMMA GEMM (mma.sync bf16 hi/lo x3): out = A * W^T + bias.
// CTA tile 128x128, 512 threads (16 warps, 4x4 warp grid, warp tile 32x32).
// K-chunk 32, 3-stage cp.async ring, smem rows padded to 80B (conflict-free
// ldmatrix). bid<512: main region (K=1536, i in [0,256), zero-padded A);
// bid>=512: tail region (K=256, unigram weights, i in [256,512)).
// ---------------------------------------------------------------------------
#define TM 128
#define TN 128
#define KC 32
#define ROWB 80                       // padded smem row bytes (40 bf16)
#define ARR_BYTES (128 * ROWB)        // 10240
#define OFF_AH 0
#define OFF_AL (1 * ARR_BYTES)
#define OFF_BH (2 * ARR_BYTES)
#define OFF_BL (3 * ARR_BYTES)
#define STG_BYTES (4 * ARR_BYTES)     // 40960
#define NSTG 3
#define SMEM_TOTAL (NSTG * STG_BYTES) // 122880

__global__ void __launch_bounds__(512, 1) gemm_tc_kernel(
    const float* __restrict__ b1, float* __restrict__ out)
{
    extern __shared__ char smem[];
    const uint32_t sbase = smem_u32(smem);
    const int tid = threadIdx.x;
    const int lane = tid & 31, wid = tid >> 5;
    const int wm = wid & 3, wn = wid >> 2;     // 4x4 warp grid

    const int bid   = blockIdx.x;
    const int mode  = bid >> 9;                // 0 = main, 1 = tail
    const int local = bid & 511;
    const int n0    = (local & 3) * TN;
    const int m0    = (local >> 2) * TM;
    const int KT    = mode ? EMB : KBIG;
    const int NC    = KT / KC;

    const __nv_bfloat16* Wh = mode ? g_W1h : g_Wbh;
    const __nv_bfloat16* Wl = mode ? g_W1l : g_Wbl;

    // ---- loader mapping: thread -> (row 0..127, 16B chunk 0..3) ----
    const int lr = tid >> 2;
    const int lc = tid & 3;
    const int mA = m0 + lr;
    const int bA = mA >> 8;
    const int prow = (mA & 255) + (mode ? 258 : 0);   // padded-X row
    const size_t offA = ((size_t)(bA * SEQP + prow)) * EMB + lc * 8;
    const size_t offB = ((size_t)(n0 + lr)) * KT + lc * 8;
    const uint32_t dst = (uint32_t)(lr * ROWB + lc * 16);

    // ---- ldmatrix lane addressing (byte offsets within an array) ----
    const uint32_t aRowOff = (uint32_t)((wm * 32 + (lane & 15)) * ROWB);
    const uint32_t aColOff = (uint32_t)((lane >> 4) * 16);          // 8 elems
    const uint32_t bRowOff = (uint32_t)((wn * 32 + (lane & 7) +
                                         ((lane & 16) ? 8 : 0)) * ROWB);
    const uint32_t bColOff = (uint32_t)((lane & 8) ? 16 : 0);

    float acc[2][4][4];
#pragma unroll
    for (int mt = 0; mt < 2; mt++)
#pragma unroll
        for (int g = 0; g < 4; g++)
#pragma unroll
            for (int c = 0; c < 4; c++) acc[mt][g][c] = 0.0f;

    // ---- prologue: fill stages 0 and 1 ----
#pragma unroll
    for (int st = 0; st < 2; st++) {
        uint32_t sb = sbase + st * STG_BYTES;
        int kb = st * KC;
        CPASYNC16(sb + OFF_AH + dst, g_Xh + offA + kb);
        CPASYNC16(sb + OFF_AL + dst, g_Xl + offA + kb);
        CPASYNC16(sb + OFF_BH + dst, Wh + offB + kb);
        CPASYNC16(sb + OFF_BL + dst, Wl + offB + kb);
        CP_COMMIT();
    }

    for (int kt = 0; kt < NC; kt++) {
        if (kt + 2 < NC) { CP_WAIT(1); } else { CP_WAIT(0); }
        __syncthreads();

        // refill stage (kt+2)%3 (its previous contents consumed at kt-1)
        if (kt + 2 < NC) {
            int st = (kt + 2) % NSTG;
            uint32_t sb = sbase + st * STG_BYTES;
            int kb = (kt + 2) * KC;
            CPASYNC16(sb + OFF_AH + dst, g_Xh + offA + kb);
            CPASYNC16(sb + OFF_AL + dst, g_Xl + offA + kb);
            CPASYNC16(sb + OFF_BH + dst, Wh + offB + kb);
            CPASYNC16(sb + OFF_BL + dst, Wl + offB + kb);
            CP_COMMIT();
        }

        // ---- compute on stage kt%3: 2 k16 steps ----
        const uint32_t sb = sbase + (kt % NSTG) * STG_BYTES;
#pragma unroll
        for (int s = 0; s < 2; s++) {
            const uint32_t kOff = s * 32;   // 16 elems = 32B
            uint32_t ah[2][4], al[2][4], bh4[2][4], bl4[2][4];
#pragma unroll
            for (int mt = 0; mt < 2; mt++) {
                uint32_t ra = aRowOff + mt * 16 * ROWB + kOff + aColOff;
                LDSM4(ah[mt], sb + OFF_AH + ra);
                LDSM4(al[mt], sb + OFF_AL + ra);
            }
#pragma unroll
            for (int p = 0; p < 2; p++) {
                uint32_t rb = bRowOff + p * 16 * ROWB + kOff + bColOff;
                LDSM4(bh4[p], sb + OFF_BH + rb);
                LDSM4(bl4[p], sb + OFF_BL + rb);
            }
#pragma unroll
            for (int mt = 0; mt < 2; mt++) {
#pragma unroll
                for (int g = 0; g < 4; g++) {
                    uint32_t bh0 = bh4[g >> 1][(g & 1) * 2];
                    uint32_t bh1 = bh4[g >> 1][(g & 1) * 2 + 1];
                    uint32_t bl0 = bl4[g >> 1][(g & 1) * 2];
                    uint32_t bl1 = bl4[g >> 1][(g & 1) * 2 + 1];
                    MMA_BF16(acc[mt][g], ah[mt], bh0, bh1);
                    MMA_BF16(acc[mt][g], ah[mt], bl0, bl1);
                    MMA_BF16(acc[mt][g], al[mt], bh0, bh1);
                }
            }
        }
    }

    // ---- epilogue: add bias, store fp32 ----
    const float* bias = mode ? b1 : g_bias;
    const int nbase = n0 + wn * 32 + (lane & 3) * 2;
    float bv[4][2];
#pragma unroll
    for (int g = 0; g < 4; g++) {
        bv[g][0] = bias[nbase + g * 8];
        bv[g][1] = bias[nbase + g * 8 + 1];
    }
    const int mrow = m0 + wm * 32 + (lane >> 2);
    const int bb = mrow >> 8;
#pragma unroll
    for (int mt = 0; mt < 2; mt++) {
        int i = ((mrow + mt * 16) & 255) + (mode ? 256 : 0);
        float* o0 = out + ((size_t)(bb * SEQ + i)) * DOUT + nbase;
        float* o1 = o0 + 8 * DOUT;   // row m+8 (same batch, i+8)
#pragma unroll
        for (int g = 0; g < 4; g++) {
            float2 v0, v1;
            v0.x = acc[mt][g][0] + bv[g][0];
            v0.y = acc[mt][g][1] + bv[g][1];
            v1.x = acc[mt][g][2] + bv[g][0];
            v1.y = acc[mt][g][3] + bv[g][1];
            *reinterpret_cast<float2*>(o0 + g * 8) = v0;
            *reinterpret_cast<float2*>(o1 + g * 8) = v1;
        }
    }
}

// ---------------------------------------------------------------------------
// Edge fix: subtract the zero-padding overcount at i=0,1 (fp32, exact).
// ---------------------------------------------------------------------------
__global__ void __launch_bounds__(256) edge_fix_kernel(
    const float* __restrict__ X, float* __restrict__ out)
{
    __shared__ float sx[KFIX];
    int b = blockIdx.x;
    int tid = threadIdx.x;
    int warp = tid >> 5, lane = tid & 31;
    int d = blockIdx.y * 8 + warp;

    for (int idx = tid; idx < KFIX; idx += blockDim.x)
        sx[idx] = X[(size_t)b * SEQ * EMB + idx];
    __syncthreads();

    const float* w0 = g_Wfix0 + (size_t)d * KFIX;
    const float* w1 = g_Wfix1 + (size_t)d * KFIX;
    float a0 = 0.0f, a1 = 0.0f;
#pragma unroll
    for (int t = 0; t < KFIX / 32; t++) {
        int k = lane + 32 * t;
        float xv = sx[k];
        a0 = fmaf(xv, w0[k], a0);
        a1 = fmaf(xv, w1[k], a1);
    }
#pragma unroll
    for (int off = 16; off; off >>= 1) {
        a0 += __shfl_xor_sync(0xFFFFFFFFu, a0, off);
        a1 += __shfl_xor_sync(0xFFFFFFFFu, a1, off);
    }
    if (lane == 0) {
        out[((size_t)b * SEQ + 0) * DOUT + d] -= a0 + g_bfix0[d];
        out[((size_t)b * SEQ + 1) * DOUT + d] -= a1 + g_bfix1[d];
    }
}

// ---------------------------------------------------------------------------
extern "C" void kernel_launch(void* const* d_in, const int* in_sizes, int n_in,
                              void* d_out, int out_size)
{
    const float* X  = (const float*)d_in[0];
    const float* W1 = (const float*)d_in[1];
    const float* b1 = (const float*)d_in[2];
    const float* W2 = (const float*)d_in[3];
    const float* b2 = (const float*)d_in[4];
    const float* W3 = (const float*)d_in[5];
    const float* b3 = (const float*)d_in[6];
    const float* W4 = (const float*)d_in[7];
    const float* b4 = (const float*)d_in[8];
    float* out = (float*)d_out;

    cudaFuncSetAttribute(gemm_tc_kernel,
                         cudaFuncAttributeMaxDynamicSharedMemorySize, SMEM_TOTAL);

    // 1. Fold branches + window sums into combined bf16 hi/lo weights
    combine_weights_kernel<<<(DOUT * EMB + 255) / 256, 256>>>(
        W1, b1, W2, b2, W3, b3, W4, b4);

    // 2. Split X into padded bf16 hi/lo
    int cvt_units = BATCH * SEQP * EMB / 4;
    convert_x_kernel<<<(cvt_units + 255) / 256, 256>>>(X);

    // 3. Both GEMM regions via warp-level HMMA (bid<512: main; else tail)
    gemm_tc_kernel<<<1024, 512, SMEM_TOTAL>>>(b1, out);

    // 4. Subtract zero-padding overcount at i=0,1
    edge_fix_kernel<<<dim3(BATCH, DOUT / 8), 256>>>(X, out);
}

// round 11
// speedup vs baseline: 3.8149x; 1.0768x over previous
#include <cuda_runtime.h>
#include <cuda_bf16.h>
#include <cstdint>

// Problem constants
#define BATCH 64
#define SEQ   512
#define EMB   256
#define DOUT  512
#define KBIG  1536          // 6 combined taps * EMB
#define KFIX  768           // 3 taps of x used by edge corrections
#define SEQP  (SEQ + 2)     // X padded with 2 zero rows at front (per batch)

// ---------------- device scratch (static globals: allowed) ----------------
__device__ __nv_bfloat16 g_Xh[BATCH * SEQP * EMB];   // bf16 hi of padded X
__device__ __nv_bfloat16 g_Xl[BATCH * SEQP * EMB];   // bf16 lo of padded X
__device__ __nv_bfloat16 g_Wbh[DOUT * KBIG];         // combined weights hi
__device__ __nv_bfloat16 g_Wbl[DOUT * KBIG];         // combined weights lo
__device__ __nv_bfloat16 g_W1h[DOUT * EMB];          // unigram weights hi
__device__ __nv_bfloat16 g_W1l[DOUT * EMB];          // unigram weights lo
__device__ float g_bias[DOUT];
__device__ float g_Wfix0[DOUT * KFIX];
__device__ float g_Wfix1[DOUT * KFIX];
__device__ float g_bfix0[DOUT];
__device__ float g_bfix1[DOUT];

// ---------------- baseline-PTX helpers (no sm_103a-only features) ---------
__device__ __forceinline__ uint32_t smem_u32(const void* p) {
    uint32_t a;
    asm("{ .reg .u64 t; cvta.to.shared.u64 t, %1; cvt.u32.u64 %0, t; }"
        : "=r"(a) : "l"(p));
    return a;
}

#define CPASYNC16(dst, src) \
    asm volatile("cp.async.cg.shared.global [%0], [%1], 16;" \
                 :: "r"((uint32_t)(dst)), "l"(src) : "memory")
#define CP_COMMIT()  asm volatile("cp.async.commit_group;" ::: "memory")
#define CP_WAIT(n)   asm volatile("cp.async.wait_group %0;" :: "n"(n) : "memory")

#define LDSM4(r, addr) \
    asm volatile("ldmatrix.sync.aligned.m8n8.x4.shared.b16 {%0,%1,%2,%3}, [%4];" \
        : "=r"((r)[0]), "=r"((r)[1]), "=r"((r)[2]), "=r"((r)[3]) \
        : "r"((uint32_t)(addr)))

#define MMA_BF16(c, a, b0, b1) \
    asm volatile("mma.sync.aligned.m16n8k16.row.col.f32.bf16.bf16.f32 " \
        "{%0,%1,%2,%3}, {%4,%5,%6,%7}, {%8,%9}, {%0,%1,%2,%3};" \
        : "+f"((c)[0]), "+f"((c)[1]), "+f"((c)[2]), "+f"((c)[3]) \
        : "r"((a)[0]), "r"((a)[1]), "r"((a)[2]), "r"((a)[3]), \
          "r"(b0), "r"(b1))

__device__ __forceinline__ void bsplit(float v, __nv_bfloat16& h, __nv_bfloat16& l) {
    h = __float2bfloat16(v);
    l = __float2bfloat16(v - __bfloat162float(h));
}

// ---------------------------------------------------------------------------
// Fold the 4 conv branches + window sums into a 6-tap combined conv weight
// (bf16 hi/lo split), plus edge-correction rows (fp32).
// Steady-state (i in [2,255]) tap combinations:
//   t=-2: W4[0]
//   t=-1: W3[0] + W4[0]+W4[1]
//   t= 0: W1 + W2[0] + W3[0]+W3[1] + W4[0]+W4[1]+W4[2]
//   t=+1: W2[1] + W3[1]+W3[2] + W4[1]+W4[2]+W4[3]
//   t=+2: W3[2] + W4[2]+W4[3]
//   t=+3: W4[3]
// bias_s = b1 + b2 + 2*b3 + 3*b4
// ---------------------------------------------------------------------------
__global__ void combine_weights_kernel(
    const float* __restrict__ W1, const float* __restrict__ b1,
    const float* __restrict__ W2, const float* __restrict__ b2,
    const float* __restrict__ W3, const float* __restrict__ b3,
    const float* __restrict__ W4, const float* __restrict__ b4)
{
    int idx = blockIdx.x * blockDim.x + threadIdx.x;
    if (idx >= DOUT * EMB) return;
    int d = idx / EMB, e = idx % EMB;

    float w1  = W1[d * EMB + e];
    const float* w2 = W2 + (size_t)(d * EMB + e) * 2;
    const float* w3 = W3 + (size_t)(d * EMB + e) * 3;
    const float* w4 = W4 + (size_t)(d * EMB + e) * 4;
    float w20 = w2[0], w21 = w2[1];
    float w30 = w3[0], w31 = w3[1], w32 = w3[2];
    float w40 = w4[0], w41 = w4[1], w42 = w4[2], w43 = w4[3];

    float taps[6];
    taps[0] = w40;
    taps[1] = w30 + w40 + w41;
    taps[2] = w1 + w20 + w30 + w31 + w40 + w41 + w42;
    taps[3] = w21 + w31 + w32 + w41 + w42 + w43;
    taps[4] = w32 + w42 + w43;
    taps[5] = w43;
#pragma unroll
    for (int t = 0; t < 6; t++) {
        size_t o = (size_t)d * KBIG + t * EMB + e;
        bsplit(taps[t], g_Wbh[o], g_Wbl[o]);
    }
    bsplit(w1, g_W1h[d * EMB + e], g_W1l[d * EMB + e]);

    float* f0 = g_Wfix0 + (size_t)d * KFIX;
    float* f1 = g_Wfix1 + (size_t)d * KFIX;
    f0[0 * EMB + e] = w31 + w41 + w42;
    f0[1 * EMB + e] = w32 + w42 + w43;
    f0[2 * EMB + e] = w43;
    f1[0 * EMB + e] = w41;
    f1[1 * EMB + e] = w42;
    f1[2 * EMB + e] = w43;

    if (e == 0) {
        g_bias[d]  = b1[d] + b2[d] + 2.0f * b3[d] + 3.0f * b4[d];
        g_bfix0[d] = b3[d] + 2.0f * b4[d];
        g_bfix1[d] = b4[d];
    }
}

// ---------------------------------------------------------------------------
// Convert X (fp32) into padded bf16 hi/lo arrays: rows 0,1 zero, r>=2 = X[r-2].
// ---------------------------------------------------------------------------
__global__ void convert_x_kernel(const float* __restrict__ X)
{
    int u = blockIdx.x * blockDim.x + threadIdx.x;          // one float4 unit
    if (u >= BATCH * SEQP * EMB / 4) return;
    int e4  = u & 63;
    int row = u >> 6;            // b*SEQP + r
    int r   = row % SEQP;
    __nv_bfloat16 h[4], l[4];
    if (r < 2) {
#pragma unroll
        for (int j = 0; j < 4; j++) { h[j] = __float2bfloat16(0.f); l[j] = h[j]; }
    } else {
        int b = row / SEQP;
        float4 v = *reinterpret_cast<const float4*>(
            X + ((size_t)(b * SEQ + (r - 2))) * EMB + e4 * 4);
        float a[4] = {v.x, v.y, v.z, v.w};
#pragma unroll
        for (int j = 0; j < 4; j++) bsplit(a[j], h[j], l[j]);
    }
    size_t o = (size_t)row * EMB + e4 * 4;
    *reinterpret_cast<__nv_bfloat162*>(g_Xh + o)     = __halves2bfloat162(h[0], h[1]);
    *reinterpret_cast<__nv_bfloat162*>(g_Xh + o + 2) = __halves2bfloat162(h[2], h[3]);
    *reinterpret_cast<__nv_bfloat162*>(g_Xl + o)     = __halves2bfloat162(l[0], l[1]);
    *reinterpret_cast<__nv_bfloat162*>(g_Xl + o + 2) = __halves2bfloat162(l[2], l[3]);
}

// ---------------------------------------------------------------------------
// Warp-level HMMA GEMM (mma.sync bf16 hi/lo x3): out = A * W^T + bias.
// CTA tile 128x256, 512 threads (16 warps, 4(m)x4(n) grid, warp tile 32x64).
// K-chunk 32, 3-stage cp.async ring (180KB smem), rows padded to 80B
// (conflict-free ldmatrix). bid<256: main (K=1536); bid>=256: tail (K=256,
// unigram) — tail last so the final partial wave is cheap.
// ---------------------------------------------------------------------------
#define TM 128
#define TN 256
#define KC 32
#define ROWB 80                        // padded smem row bytes (40 bf16)
#define A_BYTES (128 * ROWB)           // 10240
#define B_BYTES (256 * ROWB)           // 20480
#define OFF_AH 0
#define OFF_AL (A_BYTES)
#define OFF_BH (2 * A_BYTES)
#define OFF_BL (2 * A_BYTES + B_BYTES)
#define STG_BYTES (2 * A_BYTES + 2 * B_BYTES)   // 61440
#define NSTG 3
#define SMEM_TOTAL (NSTG * STG_BYTES)           // 184320

__global__ void __launch_bounds__(512, 1) gemm_tc_kernel(
    const float* __restrict__ b1, float* __restrict__ out)
{
    extern __shared__ char smem[];
    const uint32_t sbase = smem_u32(smem);
    const int tid = threadIdx.x;
    const int lane = tid & 31, wid = tid >> 5;
    const int wm = wid & 3, wn = wid >> 2;     // 4x4 warp grid

    const int bid   = blockIdx.x;
    const int mode  = bid >> 8;                // 0 = main (K=1536), 1 = tail
    const int local = bid & 255;
    const int n0    = (local & 1) * TN;
    const int m0    = (local >> 1) * TM;
    const int KT    = mode ? EMB : KBIG;
    const int NC    = KT / KC;                 // 48 or 8

    const __nv_bfloat16* Wh = mode ? g_W1h : g_Wbh;
    const __nv_bfloat16* Wl = mode ? g_W1l : g_Wbl;

    // ---- loader mapping ----
    // A: 128 rows x 4 chunks(16B) = 512 tasks (1/thread, x2 for hi/lo)
    // B: 256 rows x 4 chunks = 1024 tasks (2/thread, x2 for hi/lo)
    const int lr = tid >> 2;
    const int lc = tid & 3;
    const int mA = m0 + lr;
    const int bA = mA >> 8;
    const int prow = (mA & 255) + (mode ? 258 : 0);    // padded-X row
    const size_t offA  = ((size_t)(bA * SEQP + prow)) * EMB + lc * 8;
    const size_t offB0 = ((size_t)(n0 + lr)) * KT + lc * 8;
    const size_t offB1 = ((size_t)(n0 + lr + 128)) * KT + lc * 8;
    const uint32_t dstA  = (uint32_t)(lr * ROWB + lc * 16);
    const uint32_t dstB0 = dstA;
    const uint32_t dstB1 = (uint32_t)((lr + 128) * ROWB + lc * 16);

    // ---- ldmatrix lane addressing ----
    const uint32_t aRowOff = (uint32_t)((wm * 32 + (lane & 15)) * ROWB)
                           + (uint32_t)((lane >> 4) * 16);
    const uint32_t bRowOff = (uint32_t)((wn * 64 + (lane & 7) +
                                         ((lane & 16) ? 8 : 0)) * ROWB)
                           + (uint32_t)((lane & 8) ? 16 : 0);

    float acc[2][8][4];
#pragma unroll
    for (int mt = 0; mt < 2; mt++)
#pragma unroll
        for (int g = 0; g < 8; g++)
#pragma unroll
            for (int c = 0; c < 4; c++) acc[mt][g][c] = 0.0f;

    // ---- stage filler ----
    auto load_stage = [&](int kb, int st) {
        uint32_t sb = sbase + st * STG_BYTES;
        CPASYNC16(sb + OFF_AH + dstA,  g_Xh + offA  + kb);
        CPASYNC16(sb + OFF_AL + dstA,  g_Xl + offA  + kb);
        CPASYNC16(sb + OFF_BH + dstB0, Wh + offB0 + kb);
        CPASYNC16(sb + OFF_BH + dstB1, Wh + offB1 + kb);
        CPASYNC16(sb + OFF_BL + dstB0, Wl + offB0 + kb);
        CPASYNC16(sb + OFF_BL + dstB1, Wl + offB1 + kb);
        CP_COMMIT();
    };

    // ---- prologue: fill stages 0 and 1 ----
    load_stage(0, 0);
    load_stage(KC, 1);

    for (int kt = 0; kt < NC; kt++) {
        if (kt + 2 < NC) { CP_WAIT(1); } else { CP_WAIT(0); }
        __syncthreads();

        // refill stage (kt+2)%3 (its previous contents consumed at kt-1)
        if (kt + 2 < NC) load_stage((kt + 2) * KC, (kt + 2) % NSTG);

        // ---- compute on stage kt%3: 2 k16 steps ----
        const uint32_t sb = sbase + (kt % NSTG) * STG_BYTES;
#pragma unroll
        for (int s = 0; s < 2; s++) {
            const uint32_t kOff = s * 32;   // 16 elems = 32B
            uint32_t ah[2][4], al[2][4];
#pragma unroll
            for (int mt = 0; mt < 2; mt++) {
                uint32_t ra = aRowOff + mt * 16 * ROWB + kOff;
                LDSM4(ah[mt], sb + OFF_AH + ra);
                LDSM4(al[mt], sb + OFF_AL + ra);
            }
#pragma unroll
            for (int p = 0; p < 4; p++) {
                uint32_t rb = bRowOff + p * 16 * ROWB + kOff;
                uint32_t bh[4], bl[4];
                LDSM4(bh, sb + OFF_BH + rb);
                LDSM4(bl, sb + OFF_BL + rb);
#pragma unroll
                for (int mt = 0; mt < 2; mt++) {
                    MMA_BF16(acc[mt][2 * p],     ah[mt], bh[0], bh[1]);
                    MMA_BF16(acc[mt][2 * p],     ah[mt], bl[0], bl[1]);
                    MMA_BF16(acc[mt][2 * p],     al[mt], bh[0], bh[1]);
                    MMA_BF16(acc[mt][2 * p + 1], ah[mt], bh[2], bh[3]);
                    MMA_BF16(acc[mt][2 * p + 1], ah[mt], bl[2], bl[3]);
                    MMA_BF16(acc[mt][2 * p + 1], al[mt], bh[2], bh[3]);
                }
            }
        }
    }

    // ---- epilogue: add bias, store fp32 ----
    const float* bias = mode ? b1 : g_bias;
    const int nbase = n0 + wn * 64 + (lane & 3) * 2;
    float bv[8][2];
#pragma unroll
    for (int g = 0; g < 8; g++) {
        bv[g][0] = bias[nbase + g * 8];
        bv[g][1] = bias[nbase + g * 8 + 1];
    }
    const int mrow = m0 + wm * 32 + (lane >> 2);
    const int bb = mrow >> 8;
#pragma unroll
    for (int mt = 0; mt < 2; mt++) {
        int i = ((mrow + mt * 16) & 255) + (mode ? 256 : 0);
        float* o0 = out + ((size_t)(bb * SEQ + i)) * DOUT + nbase;
        float* o1 = o0 + 8 * DOUT;   // row m+8 (same batch, i+8)
#pragma unroll
        for (int g = 0; g < 8; g++) {
            float2 v0, v1;
            v0.x = acc[mt][g][0] + bv[g][0];
            v0.y = acc[mt][g][1] + bv[g][1];
            v1.x = acc[mt][g][2] + bv[g][0];
            v1.y = acc[mt][g][3] + bv[g][1];
            *reinterpret_cast<float2*>(o0 + g * 8) = v0;
            *reinterpret_cast<float2*>(o1 + g * 8) = v1;
        }
    }
}

// ---------------------------------------------------------------------------
// Edge fix: subtract the zero-padding overcount at i=0,1 (fp32, exact).
// Block = (8 batches x 8 d): weights read once per k into registers and
// reused across 8 batches staged in smem -> 8x less Wfix traffic.
// grid = (BATCH/8, DOUT/8).
// ---------------------------------------------------------------------------
__global__ void __launch_bounds__(256) edge_fix_kernel(
    const float* __restrict__ X, float* __restrict__ out)
{
    __shared__ float sx[8][KFIX];
    int b0 = blockIdx.x * 8;
    int tid = threadIdx.x;
    int warp = tid >> 5, lane = tid & 31;
    int d = blockIdx.y * 8 + warp;

    for (int u = tid; u < 8 * KFIX; u += 256) {
        int bb = u / KFIX, k = u % KFIX;
        sx[bb][k] = X[(size_t)(b0 + bb) * SEQ * EMB + k];
    }
    __syncthreads();

    const float* w0 = g_Wfix0 + (size_t)d * KFIX;
    const float* w1 = g_Wfix1 + (size_t)d * KFIX;
    float a0[8], a1[8];
#pragma unroll
    for (int bb = 0; bb < 8; bb++) { a0[bb] = 0.0f; a1[bb] = 0.0f; }

#pragma unroll 4
    for (int t = 0; t < KFIX / 32; t++) {
        int k = lane + 32 * t;
        float v0 = w0[k], v1 = w1[k];
#pragma unroll
        for (int bb = 0; bb < 8; bb++) {
            float xv = sx[bb][k];
            a0[bb] = fmaf(xv, v0, a0[bb]);
            a1[bb] = fmaf(xv, v1, a1[bb]);
        }
    }
#pragma unroll
    for (int off = 16; off; off >>= 1) {
#pragma unroll
        for (int bb = 0; bb < 8; bb++) {
            a0[bb] += __shfl_xor_sync(0xFFFFFFFFu, a0[bb], off);
            a1[bb] += __shfl_xor_sync(0xFFFFFFFFu, a1[bb], off);
        }
    }
    if (lane == 0) {
        float c0 = g_bfix0[d], c1 = g_bfix1[d];
#pragma unroll
        for (int bb = 0; bb < 8; bb++) {
            size_t base = (size_t)(b0 + bb) * SEQ * DOUT;
            out[base + d]        -= a0[bb] + c0;
            out[base + DOUT + d] -= a1[bb] + c1;
        }
    }
}

// ---------------------------------------------------------------------------
extern "C" void kernel_launch(void* const* d_in, const int* in_sizes, int n_in,
                              void* d_out, int out_size)
{
    const float* X  = (const float*)d_in[0];
    const float* W1 = (const float*)d_in[1];
    const float* b1 = (const float*)d_in[2];
    const float* W2 = (const float*)d_in[3];
    const float* b2 = (const float*)d_in[4];
    const float* W3 = (const float*)d_in[5];
    const float* b3 = (const float*)d_in[6];
    const float* W4 = (const float*)d_in[7];
    const float* b4 = (const float*)d_in[8];
    float* out = (float*)d_out;

    cudaFuncSetAttribute(gemm_tc_kernel,
                         cudaFuncAttributeMaxDynamicSharedMemorySize, SMEM_TOTAL);

    // 1. Fold branches + window sums into combined bf16 hi/lo weights
    combine_weights_kernel<<<(DOUT * EMB + 255) / 256, 256>>>(
        W1, b1, W2, b2, W3, b3, W4, b4);

    // 2. Split X into padded bf16 hi/lo
    int cvt_units = BATCH * SEQP * EMB / 4;
    convert_x_kernel<<<(cvt_units + 255) / 256, 256>>>(X);

    // 3. Both GEMM regions via warp-level HMMA (bid<256: main; else tail)
    gemm_tc_kernel<<<512, 512, SMEM_TOTAL>>>(b1, out);

    // 4. Subtract zero-padding overcount at i=0,1
    edge_fix_kernel<<<dim3(BATCH / 8, DOUT / 8), 256>>>(X, out);
}

// round 13
// speedup vs baseline: 4.0179x; 1.0532x over previous
#include <cuda_runtime.h>
#include <cuda_bf16.h>
#include <cstdint>

// Problem constants
#define BATCH 64
#define SEQ   512
#define EMB   256
#define DOUT  512
#define KBIG  1536          // 6 combined taps * EMB
#define KFIX  768           // 3 taps of x used by edge corrections
#define SEQP  (SEQ + 2)     // X padded with 2 zero rows at front (per batch)

// ---------------- device scratch (static globals: allowed) ----------------
__device__ __nv_bfloat16 g_Xh[BATCH * SEQP * EMB];   // bf16 hi of padded X
__device__ __nv_bfloat16 g_Xl[BATCH * SEQP * EMB];   // bf16 lo of padded X
__device__ __nv_bfloat16 g_Wbh[DOUT * KBIG];         // combined weights hi
__device__ __nv_bfloat16 g_Wbl[DOUT * KBIG];         // combined weights lo
__device__ __nv_bfloat16 g_W1h[DOUT * EMB];          // unigram weights hi
__device__ __nv_bfloat16 g_W1l[DOUT * EMB];          // unigram weights lo
__device__ float g_bias[DOUT];
__device__ float g_Wfix0[DOUT * KFIX];
__device__ float g_Wfix1[DOUT * KFIX];
__device__ float g_bfix0[DOUT];
__device__ float g_bfix1[DOUT];
__device__ float g_corr[BATCH * 2 * DOUT];           // edge corrections (i=0,1)

// ---------------- baseline-PTX helpers (no sm_103a-only features) ---------
__device__ __forceinline__ uint32_t smem_u32(const void* p) {
    uint32_t a;
    asm("{ .reg .u64 t; cvta.to.shared.u64 t, %1; cvt.u32.u64 %0, t; }"
        : "=r"(a) : "l"(p));
    return a;
}

#define CPASYNC16(dst, src) \
    asm volatile("cp.async.cg.shared.global [%0], [%1], 16;" \
                 :: "r"((uint32_t)(dst)), "l"(src) : "memory")
#define CP_COMMIT()  asm volatile("cp.async.commit_group;" ::: "memory")
#define CP_WAIT(n)   asm volatile("cp.async.wait_group %0;" :: "n"(n) : "memory")

#define LDSM4(r, addr) \
    asm volatile("ldmatrix.sync.aligned.m8n8.x4.shared.b16 {%0,%1,%2,%3}, [%4];" \
        : "=r"((r)[0]), "=r"((r)[1]), "=r"((r)[2]), "=r"((r)[3]) \
        : "r"((uint32_t)(addr)))

#define MMA_BF16(c, a, b0, b1) \
    asm volatile("mma.sync.aligned.m16n8k16.row.col.f32.bf16.bf16.f32 " \
        "{%0,%1,%2,%3}, {%4,%5,%6,%7}, {%8,%9}, {%0,%1,%2,%3};" \
        : "+f"((c)[0]), "+f"((c)[1]), "+f"((c)[2]), "+f"((c)[3]) \
        : "r"((a)[0]), "r"((a)[1]), "r"((a)[2]), "r"((a)[3]), \
          "r"(b0), "r"(b1))

__device__ __forceinline__ void bsplit(float v, __nv_bfloat16& h, __nv_bfloat16& l) {
    h = __float2bfloat16(v);
    l = __float2bfloat16(v - __bfloat162float(h));
}

// ---------------------------------------------------------------------------
// Fold the 4 conv branches + window sums into a 6-tap combined conv weight
// (bf16 hi/lo split), plus edge-correction rows (fp32).
// Steady-state (i in [2,255]) tap combinations:
//   t=-2: W4[0]
//   t=-1: W3[0] + W4[0]+W4[1]
//   t= 0: W1 + W2[0] + W3[0]+W3[1] + W4[0]+W4[1]+W4[2]
//   t=+1: W2[1] + W3[1]+W3[2] + W4[1]+W4[2]+W4[3]
//   t=+2: W3[2] + W4[2]+W4[3]
//   t=+3: W4[3]
// bias_s = b1 + b2 + 2*b3 + 3*b4
// ---------------------------------------------------------------------------
__global__ void combine_weights_kernel(
    const float* __restrict__ W1, const float* __restrict__ b1,
    const float* __restrict__ W2, const float* __restrict__ b2,
    const float* __restrict__ W3, const float* __restrict__ b3,
    const float* __restrict__ W4, const float* __restrict__ b4)
{
    int idx = blockIdx.x * blockDim.x + threadIdx.x;
    if (idx >= DOUT * EMB) return;
    int d = idx / EMB, e = idx % EMB;

    float w1  = W1[d * EMB + e];
    const float* w2 = W2 + (size_t)(d * EMB + e) * 2;
    const float* w3 = W3 + (size_t)(d * EMB + e) * 3;
    const float* w4 = W4 + (size_t)(d * EMB + e) * 4;
    float w20 = w2[0], w21 = w2[1];
    float w30 = w3[0], w31 = w3[1], w32 = w3[2];
    float w40 = w4[0], w41 = w4[1], w42 = w4[2], w43 = w4[3];

    float taps[6];
    taps[0] = w40;
    taps[1] = w30 + w40 + w41;
    taps[2] = w1 + w20 + w30 + w31 + w40 + w41 + w42;
    taps[3] = w21 + w31 + w32 + w41 + w42 + w43;
    taps[4] = w32 + w42 + w43;
    taps[5] = w43;
#pragma unroll
    for (int t = 0; t < 6; t++) {
        size_t o = (size_t)d * KBIG + t * EMB + e;
        bsplit(taps[t], g_Wbh[o], g_Wbl[o]);
    }
    bsplit(w1, g_W1h[d * EMB + e], g_W1l[d * EMB + e]);

    float* f0 = g_Wfix0 + (size_t)d * KFIX;
    float* f1 = g_Wfix1 + (size_t)d * KFIX;
    f0[0 * EMB + e] = w31 + w41 + w42;
    f0[1 * EMB + e] = w32 + w42 + w43;
    f0[2 * EMB + e] = w43;
    f1[0 * EMB + e] = w41;
    f1[1 * EMB + e] = w42;
    f1[2 * EMB + e] = w43;

    if (e == 0) {
        g_bias[d]  = b1[d] + b2[d] + 2.0f * b3[d] + 3.0f * b4[d];
        g_bfix0[d] = b3[d] + 2.0f * b4[d];
        g_bfix1[d] = b4[d];
    }
}

// ---------------------------------------------------------------------------
// Fused prep kernel (single launch, independent block groups):
//  blocks [0, CVT_BLOCKS): convert X (fp32) into padded bf16 hi/lo arrays
//     (rows 0,1 zero, r>=2 = X[r-2]).
//  blocks [CVT_BLOCKS, CVT_BLOCKS+512): compute edge corrections g_corr
//     (reads X + g_Wfix written by combine_weights in the PREVIOUS launch;
//      no dependency on GEMM output -> GEMM epilogue subtracts g_corr).
// ---------------------------------------------------------------------------
#define CVT_BLOCKS (BATCH * SEQP * EMB / 4 / 256)   // 8224 (exact)

__global__ void __launch_bounds__(256) prep_kernel(const float* __restrict__ X)
{
    __shared__ float sx[8][KFIX];
    const int tid = threadIdx.x;

    if (blockIdx.x < CVT_BLOCKS) {
        // ---- convert branch ----
        int u = blockIdx.x * 256 + tid;          // one float4 unit
        int e4  = u & 63;
        int row = u >> 6;            // b*SEQP + r
        int r   = row % SEQP;
        __nv_bfloat16 h[4], l[4];
        if (r < 2) {
#pragma unroll
            for (int j = 0; j < 4; j++) { h[j] = __float2bfloat16(0.f); l[j] = h[j]; }
        } else {
            int b = row / SEQP;
            float4 v = *reinterpret_cast<const float4*>(
                X + ((size_t)(b * SEQ + (r - 2))) * EMB + e4 * 4);
            float a[4] = {v.x, v.y, v.z, v.w};
#pragma unroll
            for (int j = 0; j < 4; j++) bsplit(a[j], h[j], l[j]);
        }
        size_t o = (size_t)row * EMB + e4 * 4;
        *reinterpret_cast<__nv_bfloat162*>(g_Xh + o)     = __halves2bfloat162(h[0], h[1]);
        *reinterpret_cast<__nv_bfloat162*>(g_Xh + o + 2) = __halves2bfloat162(h[2], h[3]);
        *reinterpret_cast<__nv_bfloat162*>(g_Xl + o)     = __halves2bfloat162(l[0], l[1]);
        *reinterpret_cast<__nv_bfloat162*>(g_Xl + o + 2) = __halves2bfloat162(l[2], l[3]);
        return;
    }

    // ---- edge-correction branch ----
    int cb = blockIdx.x - CVT_BLOCKS;            // 0..511
    int b0 = (cb & 7) * 8;
    int d  = (cb >> 3) * 8 + (tid >> 5);
    int lane = tid & 31;

    for (int u = tid; u < 8 * KFIX; u += 256) {
        int bb = u / KFIX, k = u % KFIX;
        sx[bb][k] = X[(size_t)(b0 + bb) * SEQ * EMB + k];
    }
    __syncthreads();

    const float* w0 = g_Wfix0 + (size_t)d * KFIX;
    const float* w1 = g_Wfix1 + (size_t)d * KFIX;
    float a0[8], a1[8];
#pragma unroll
    for (int bb = 0; bb < 8; bb++) { a0[bb] = 0.0f; a1[bb] = 0.0f; }

#pragma unroll 4
    for (int t = 0; t < KFIX / 32; t++) {
        int k = lane + 32 * t;
        float v0 = w0[k], v1 = w1[k];
#pragma unroll
        for (int bb = 0; bb < 8; bb++) {
            float xv = sx[bb][k];
            a0[bb] = fmaf(xv, v0, a0[bb]);
            a1[bb] = fmaf(xv, v1, a1[bb]);
        }
    }
#pragma unroll
    for (int off = 16; off; off >>= 1) {
#pragma unroll
        for (int bb = 0; bb < 8; bb++) {
            a0[bb] += __shfl_xor_sync(0xFFFFFFFFu, a0[bb], off);
            a1[bb] += __shfl_xor_sync(0xFFFFFFFFu, a1[bb], off);
        }
    }
    if (lane == 0) {
        float c0 = g_bfix0[d], c1 = g_bfix1[d];
#pragma unroll
        for (int bb = 0; bb < 8; bb++) {
            g_corr[(size_t)((b0 + bb) * 2 + 0) * DOUT + d] = a0[bb] + c0;
            g_corr[(size_t)((b0 + bb) * 2 + 1) * DOUT + d] = a1[bb] + c1;
        }
    }
}

// ---------------------------------------------------------------------------
// Warp-level HMMA GEMM (mma.sync bf16 hi/lo x3): out = A * W^T + bias - corr.
// CTA tile 128x128, 256 threads (8 warps: 4(m) x 2(n), warp tile 32x64).
// K-chunk 32, 2-stage cp.async ring (80KB smem -> 2 CTAs/SM for latency
// hiding), rows padded to 80B (conflict-free ldmatrix).
// bid<512: main (K=1536, i in [0,256), zero-padded A, subtract g_corr at
// i=0,1); bid>=512: tail (K=256, unigram).
// ---------------------------------------------------------------------------
#define TM 128
#define TN 128
#define KC 32
#define ROWB 80                        // padded smem row bytes (40 bf16)
#define A_BYTES (128 * ROWB)           // 10240
#define B_BYTES (128 * ROWB)           // 10240
#define OFF_AH 0
#define OFF_AL (A_BYTES)
#define OFF_BH (2 * A_BYTES)
#define OFF_BL (2 * A_BYTES + B_BYTES)
#define STG_BYTES (2 * A_BYTES + 2 * B_BYTES)   // 40960
#define NSTG 2
#define SMEM_TOTAL (NSTG * STG_BYTES)           // 81920

__global__ void __launch_bounds__(256, 2) gemm_tc_kernel(
    const float* __restrict__ b1, float* __restrict__ out)
{
    extern __shared__ char smem[];
    const uint32_t sbase = smem_u32(smem);
    const int tid = threadIdx.x;
    const int lane = tid & 31, wid = tid >> 5;
    const int wm = wid & 3, wn = wid >> 2;     // 4(m) x 2(n) warp grid

    const int bid   = blockIdx.x;
    const int mode  = bid >> 9;                // 0 = main (K=1536), 1 = tail
    const int local = bid & 511;
    const int n0    = (local & 3) * TN;
    const int m0    = (local >> 2) * TM;
    const int KT    = mode ? EMB : KBIG;
    const int NC    = KT / KC;                 // 48 or 8

    const __nv_bfloat16* Wh = mode ? g_W1h : g_Wbh;
    const __nv_bfloat16* Wl = mode ? g_W1l : g_Wbl;

    // ---- loader mapping: each thread fills rows (lr, lr+64), chunk lc ----
    const int lr = tid >> 2;          // 0..63
    const int lc = tid & 3;
    size_t offA[2], offB[2];
    uint32_t dstL[2];
#pragma unroll
    for (int hh = 0; hh < 2; hh++) {
        int r = lr + hh * 64;
        int mA = m0 + r;
        int bA = mA >> 8;
        int prow = (mA & 255) + (mode ? 258 : 0);   // padded-X row
        offA[hh] = ((size_t)(bA * SEQP + prow)) * EMB + lc * 8;
        offB[hh] = ((size_t)(n0 + r)) * KT + lc * 8;
        dstL[hh] = (uint32_t)(r * ROWB + lc * 16);
    }

    // ---- ldmatrix lane addressing ----
    const uint32_t aRowOff = (uint32_t)((wm * 32 + (lane & 15)) * ROWB)
                           + (uint32_t)((lane >> 4) * 16);
    const uint32_t bRowOff = (uint32_t)((wn * 64 + (lane & 7) +
                                         ((lane & 16) ? 8 : 0)) * ROWB)
                           + (uint32_t)((lane & 8) ? 16 : 0);

    float acc[2][8][4];
#pragma unroll
    for (int mt = 0; mt < 2; mt++)
#pragma unroll
        for (int g = 0; g < 8; g++)
#pragma unroll
            for (int c = 0; c < 4; c++) acc[mt][g][c] = 0.0f;

    // ---- stage filler ----
    auto load_stage = [&](int kb, int st) {
        uint32_t sb = sbase + st * STG_BYTES;
#pragma unroll
        for (int hh = 0; hh < 2; hh++) {
            CPASYNC16(sb + OFF_AH + dstL[hh], g_Xh + offA[hh] + kb);
            CPASYNC16(sb + OFF_AL + dstL[hh], g_Xl + offA[hh] + kb);
            CPASYNC16(sb + OFF_BH + dstL[hh], Wh + offB[hh] + kb);
            CPASYNC16(sb + OFF_BL + dstL[hh], Wl + offB[hh] + kb);
        }
        CP_COMMIT();
    };

    load_stage(0, 0);   // prologue

    for (int kt = 0; kt < NC; kt++) {
        if (kt + 1 < NC) {
            load_stage((kt + 1) * KC, (kt + 1) & 1);
            CP_WAIT(1);
        } else {
            CP_WAIT(0);
        }
        __syncthreads();

        // ---- compute on stage kt&1: 2 k16 steps ----
        const uint32_t sb = sbase + (kt & 1) * STG_BYTES;
#pragma unroll
        for (int s = 0; s < 2; s++) {
            const uint32_t kOff = s * 32;   // 16 elems = 32B
            uint32_t ah[2][4], al[2][4];
#pragma unroll
            for (int mt = 0; mt < 2; mt++) {
                uint32_t ra = aRowOff + mt * 16 * ROWB + kOff;
                LDSM4(ah[mt], sb + OFF_AH + ra);
                LDSM4(al[mt], sb + OFF_AL + ra);
            }
#pragma unroll
            for (int p = 0; p < 4; p++) {
                uint32_t rb = bRowOff + p * 16 * ROWB + kOff;
                uint32_t bh[4], bl[4];
                LDSM4(bh, sb + OFF_BH + rb);
                LDSM4(bl, sb + OFF_BL + rb);
#pragma unroll
                for (int mt = 0; mt < 2; mt++) {
                    MMA_BF16(acc[mt][2 * p],     ah[mt], bh[0], bh[1]);
                    MMA_BF16(acc[mt][2 * p],     ah[mt], bl[0], bl[1]);
                    MMA_BF16(acc[mt][2 * p],     al[mt], bh[0], bh[1]);
                    MMA_BF16(acc[mt][2 * p + 1], ah[mt], bh[2], bh[3]);
                    MMA_BF16(acc[mt][2 * p + 1], ah[mt], bl[2], bl[3]);
                    MMA_BF16(acc[mt][2 * p + 1], al[mt], bh[2], bh[3]);
                }
            }
        }
        __syncthreads();   // all reads of this buffer done before next refill
    }

    // ---- epilogue: add bias, subtract edge corr (i<2), store fp32 ----
    const float* bias = mode ? b1 : g_bias;
    const int nbase = n0 + wn * 64 + (lane & 3) * 2;
    float bv[8][2];
#pragma unroll
    for (int g = 0; g < 8; g++) {
        bv[g][0] = bias[nbase + g * 8];
        bv[g][1] = bias[nbase + g * 8 + 1];
    }
    const int mrow = m0 + wm * 32 + (lane >> 2);
    const int bb = mrow >> 8;
#pragma unroll
    for (int mt = 0; mt < 2; mt++) {
        int i = ((mrow + mt * 16) & 255) + (mode ? 256 : 0);
        float* o0 = out + ((size_t)(bb * SEQ + i)) * DOUT + nbase;
        float* o1 = o0 + 8 * DOUT;   // row m+8 (same batch, i+8)
        const bool fix = (mode == 0) && (i < 2);
        const float* cr = g_corr + (size_t)(bb * 2 + i) * DOUT + nbase;
#pragma unroll
        for (int g = 0; g < 8; g++) {
            float2 v0, v1;
            v0.x = acc[mt][g][0] + bv[g][0];
            v0.y = acc[mt][g][1] + bv[g][1];
            v1.x = acc[mt][g][2] + bv[g][0];
            v1.y = acc[mt][g][3] + bv[g][1];
            if (fix) {
                v0.x -= cr[g * 8];
                v0.y -= cr[g * 8 + 1];
            }
            *reinterpret_cast<float2*>(o0 + g * 8) = v0;
            *reinterpret_cast<float2*>(o1 + g * 8) = v1;
        }
    }
}

// ---------------------------------------------------------------------------
extern "C" void kernel_launch(void* const* d_in, const int* in_sizes, int n_in,
                              void* d_out, int out_size)
{
    const float* X  = (const float*)d_in[0];
    const float* W1 = (const float*)d_in[1];
    const float* b1 = (const float*)d_in[2];
    const float* W2 = (const float*)d_in[3];
    const float* b2 = (const float*)d_in[4];
    const float* W3 = (const float*)d_in[5];
    const float* b3 = (const float*)d_in[6];
    const float* W4 = (const float*)d_in[7];
    const float* b4 = (const float*)d_in[8];
    float* out = (float*)d_out;

    cudaFuncSetAttribute(gemm_tc_kernel,
                         cudaFuncAttributeMaxDynamicSharedMemorySize, SMEM_TOTAL);

    // 1. Fold branches + window sums into combined bf16 hi/lo weights + Wfix
    combine_weights_kernel<<<(DOUT * EMB + 255) / 256, 256>>>(
        W1, b1, W2, b2, W3, b3, W4, b4);

    // 2. Fused: split X into padded bf16 hi/lo  +  compute edge corrections
    prep_kernel<<<CVT_BLOCKS + 512, 256>>>(X);

    // 3. Both GEMM regions via warp-level HMMA, 2 CTAs/SM
    //    (bid<512: main; else tail). Epilogue applies bias and g_corr.
    gemm_tc_kernel<<<1024, 256, SMEM_TOTAL>>>(b1, out);
}